// round 15
// baseline (speedup 1.0000x reference)
#include <cuda_runtime.h>
#include <math.h>

#define BB 4
#define NN 256
#define CC 256
#define HH 8
#define FF 64
#define HF 512

typedef unsigned long long ull;

__device__ float g_glt[BB * HH * NN * 68];  // g_l transposed+padded [b][h][n][68]
__device__ float g_gr[BB * NN * HF];
__device__ float g_el[BB * NN * HH];        // 0.6 * dot(g_l, w), [b][n][h]
__device__ float g_er[BB * NN * HH];        // 0.6 * dot(g_r, w)
__device__ float g_part[2][BB * NN * HF];
__device__ unsigned g_cnt[BB * 32];         // zero-init; reset after use

// ---- packed f32x2 helpers ----
__device__ __forceinline__ ull f2add(ull a, ull b) {
    ull r; asm("add.rn.f32x2 %0,%1,%2;" : "=l"(r) : "l"(a), "l"(b)); return r;
}
__device__ __forceinline__ ull f2fma(ull a, ull b, ull c) {
    ull r; asm("fma.rn.f32x2 %0,%1,%2,%3;" : "=l"(r) : "l"(a), "l"(b), "l"(c)); return r;
}
__device__ __forceinline__ ull pk(float lo, float hi) {
    ull r; asm("mov.b64 %0,{%1,%2};" : "=l"(r) : "f"(lo), "f"(hi)); return r;
}
__device__ __forceinline__ float2 upk(ull v) {
    float2 r; asm("mov.b64 {%0,%1},%2;" : "=f"(r.x), "=f"(r.y) : "l"(v)); return r;
}
__device__ __forceinline__ unsigned sm_u32(const void* p) {
    unsigned a;
    asm("{ .reg .u64 t; cvta.to.shared.u64 t, %1; cvt.u32.u64 %0, t; }"
        : "=r"(a) : "l"(p));
    return a;
}
__device__ __forceinline__ void mbar_init(unsigned m, unsigned cnt) {
    asm volatile("mbarrier.init.shared.b64 [%0], %1;" :: "r"(m), "r"(cnt) : "memory");
}
__device__ __forceinline__ void mbar_expect(unsigned m, unsigned bytes) {
    asm volatile("mbarrier.arrive.expect_tx.shared.b64 _, [%0], %1;"
                 :: "r"(m), "r"(bytes) : "memory");
}
__device__ __forceinline__ void bulk_g2s(unsigned dst, const void* src,
                                         unsigned bytes, unsigned mbar) {
    asm volatile("cp.async.bulk.shared::cta.global.mbarrier::complete_tx::bytes "
                 "[%0], [%1], %2, [%3];"
                 :: "r"(dst), "l"(src), "r"(bytes), "r"(mbar) : "memory");
}
__device__ __forceinline__ void mbar_wait(unsigned m, unsigned parity) {
    asm volatile(
        "{\n\t"
        ".reg .pred P;\n\t"
        "WL_%=:\n\t"
        "mbarrier.try_wait.parity.acquire.cta.shared::cta.b64 P, [%0], %1, 0x989680;\n\t"
        "@P bra.uni WD_%=;\n\t"
        "bra.uni WL_%=;\n\t"
        "WD_%=:\n\t"
        "}"
        :: "r"(m), "r"(parity) : "memory");
}

// ============================================================
// K1: SGEMM, 32x64 tile, 128 threads, 4x4 packed microtile, BK=32.
// grid (8,32,2) = 512 blocks -> ~3.5/SM (latency hiding).
// which=0 -> g_glt (transposed/padded); which=1 -> g_gr.
// Fused 0.6*dot(g,w) epilogue.
// ============================================================
__global__ __launch_bounds__(128) void k_gemm(const float* __restrict__ X,
                                              const float* __restrict__ Wl,
                                              const float* __restrict__ Wr,
                                              const float* __restrict__ attn_w) {
    __shared__ float As[32][36];   // [k][m], m=32
    __shared__ float Bs[32][68];
    const int which = blockIdx.z;
    const float* W = which ? Wr : Wl;
    float* E = which ? g_er : g_el;

    const int t  = threadIdx.x;
    const int tx = t & 15;
    const int ty = t >> 4;        // 0..7
    const int m0 = blockIdx.y * 32;
    const int n0 = blockIdx.x * 64;

    ull acc[4][2] = {};

    for (int k0 = 0; k0 < 256; k0 += 32) {
        {   // stage X tile transposed: per phase same kq, m spread (conflict-free)
            #pragma unroll
            for (int q = 0; q < 2; q++) {
                const int idx = q * 128 + t;
                const int m = idx & 31, kq = (idx >> 5) * 4;
                float4 xa = *(const float4*)(X + (m0 + m) * 256 + k0 + kq);
                As[kq + 0][m] = xa.x;
                As[kq + 1][m] = xa.y;
                As[kq + 2][m] = xa.z;
                As[kq + 3][m] = xa.w;
            }
        }
        {   // stage W tile
            #pragma unroll
            for (int q = 0; q < 4; q++) {
                const int idx = q * 128 + t;
                const int k = idx >> 4, c = idx & 15;
                *(float4*)(&Bs[k][c * 4]) =
                    *(const float4*)(W + (k0 + k) * 512 + n0 + c * 4);
            }
        }
        __syncthreads();
        #pragma unroll
        for (int k = 0; k < 32; k++) {
            float4 a4 = *(const float4*)(&As[k][ty * 4]);
            ulonglong2 b2 = *(const ulonglong2*)(&Bs[k][tx * 4]);
            ull p0 = pk(a4.x, a4.x), p1 = pk(a4.y, a4.y);
            ull p2 = pk(a4.z, a4.z), p3 = pk(a4.w, a4.w);
            acc[0][0] = f2fma(p0, b2.x, acc[0][0]);
            acc[0][1] = f2fma(p0, b2.y, acc[0][1]);
            acc[1][0] = f2fma(p1, b2.x, acc[1][0]);
            acc[1][1] = f2fma(p1, b2.y, acc[1][1]);
            acc[2][0] = f2fma(p2, b2.x, acc[2][0]);
            acc[2][1] = f2fma(p2, b2.y, acc[2][1]);
            acc[3][0] = f2fma(p3, b2.x, acc[3][0]);
            acc[3][1] = f2fma(p3, b2.y, acc[3][1]);
        }
        __syncthreads();
    }

    const int hh = n0 >> 6;
    float af[4][4];
    #pragma unroll
    for (int i = 0; i < 4; i++) {
        float2 lo = upk(acc[i][0]), hi = upk(acc[i][1]);
        af[i][0] = lo.x; af[i][1] = lo.y; af[i][2] = hi.x; af[i][3] = hi.y;
        const int row = m0 + ty * 4 + i;
        float4 o = make_float4(lo.x, lo.y, hi.x, hi.y);
        if (which) {
            *(float4*)(g_gr + row * 512 + n0 + tx * 4) = o;
        } else {
            const int bb = row >> 8, n = row & 255;
            *(float4*)(g_glt + ((bb * 8 + hh) * 256 + n) * 68 + tx * 4) = o;
        }
    }

    float w0 = attn_w[tx * 4 + 0], w1 = attn_w[tx * 4 + 1];
    float w2 = attn_w[tx * 4 + 2], w3 = attn_w[tx * 4 + 3];
    #pragma unroll
    for (int i = 0; i < 4; i++) {
        float part = af[i][0] * w0;
        part = fmaf(af[i][1], w1, part);
        part = fmaf(af[i][2], w2, part);
        part = fmaf(af[i][3], w3, part);
        // reduce over tx = lane bits 0..3
        part += __shfl_xor_sync(0xffffffff, part, 8);
        part += __shfl_xor_sync(0xffffffff, part, 4);
        part += __shfl_xor_sync(0xffffffff, part, 2);
        part += __shfl_xor_sync(0xffffffff, part, 1);
        if (tx == 0) E[(m0 + ty * 4 + i) * 8 + hh] = 0.6f * part;
    }
}

// ============================================================
// K2: fused attention (exact R10/R14 version). cp.async.bulk
// staging (mbarA: s_gl+s_el, mbarB: s_gr). 512 threads, IT=8,
// j-half per block, JC=16, grid 256.
// ============================================================
#define IT 8
#define JC 16
#define GIS 544      // 8*68  s_gri per-h stride
#define GLSH 1088    // 16*68 s_gl per-h slab (= 4352B, contiguous in g_glt)
#define SAS 200      // s_a per-h stride (jl*12 + il)
#define GL_SLAB_BYTES (JC * 68 * 4)          // 4352
#define EL_BYTES (JC * 8 * 4)                // 512
#define A_TX_BYTES (8 * GL_SLAB_BYTES + EL_BYTES)  // 35328
#define GR_BYTES (JC * 512 * 4)              // 32768

#define SMEM_FLOATS (4352 + 8704 + 8192 + 1152 + 1600 + 64 + 128 + 64 + 256 + 8)

__global__ __launch_bounds__(512, 2) void k_attn(const float* __restrict__ attn_w,
                                                 const int* __restrict__ adj,
                                                 float* __restrict__ out) {
    extern __shared__ float sm[];
    float* s_gri = sm;                   // [h][il*68+f]        4352
    float* s_gl  = s_gri + 4352;         // [h][jl*68+f]        8704
    float* s_gr  = s_gl + 8704;          // [jl][512]           8192
    float* s_e   = s_gr + 8192;          // [(il*16+jl)*9+h]    1152
    float* s_a   = s_e + 1152;           // [h][jl*12+il]       1600
    float* s_w   = s_a + 1600;           // 0.4*w               64
    float* s_el  = s_w + 64;             // [jl][h]             128
    float* s_er  = s_el + 128;           // 64
    float* s_mk  = s_er + 64;            // 256 floats = 1024 mask bytes
    ull*   s_mbars = (ull*)(s_mk + 256); // 2 mbarriers (16B)
    unsigned char* s_maskb = (unsigned char*)s_mk;
    ull*   s_red = (ull*)s_gl;           // aliased reduce buf
    __shared__ unsigned s_turn;

    const int t  = threadIdx.x;
    const int bx = blockIdx.x;
    const int jh = bx & 1;
    const int it = (bx >> 1) & 31;
    const int b  = bx >> 6;
    const int i0 = it * IT;
    const int jbase = jh * 128;

    const float* Gr  = g_gr + b * NN * HF;
    const float* Glt = g_glt + b * HH * NN * 68;
    const float* El  = g_el + b * NN * HH;

    const unsigned u_mbarA = sm_u32(s_mbars);
    const unsigned u_mbarB = sm_u32(s_mbars + 1);
    const unsigned u_gl    = sm_u32(s_gl);
    const unsigned u_gr    = sm_u32(s_gr);
    const unsigned u_el    = sm_u32(s_el);

    // phase-1 ids: warp = (h, ilq); phase holds 8 jl x 2 il
    const int w1 = t >> 5, lane = t & 31;
    const int h1  = w1 >> 1;
    const int ilq = w1 & 1;
    const int il_a = ilq * 2 + (lane & 1);
    const int il_b = il_a + 4;
    const int jl1  = lane >> 1;
    // phase-2 ids
    const int c4  = t & 127;
    const int ilh = (t >> 7) & 1;
    const int jq  = t >> 8;
    const int h2  = c4 >> 4;

    // prologue: mbar init first, then smem staging
    if (t == 0) { mbar_init(u_mbarA, 1); mbar_init(u_mbarB, 1); }
    if (t < 64) s_w[t] = 0.4f * attn_w[t];
    #pragma unroll
    for (int q = 0; q < 2; q++) {
        const int idx = q * 512 + t;
        const int il = idx >> 7, rest = idx & 127, h = rest >> 4, f4 = rest & 15;
        float4 v = *(const float4*)(Gr + (i0 + il) * 512 + rest * 4);
        *(float4*)(s_gri + h * GIS + il * 68 + f4 * 4) = v;
    }
    if (t < 64) s_er[t] = g_er[(b * NN + i0 + (t >> 3)) * 8 + (t & 7)];
    {
        const int4* A4 = (const int4*)adj;
        #pragma unroll
        for (int q = 0; q < 2; q++) {
            const int p = q * 512 + t;           // 0..1023 (il, jloc)
            const int il = p >> 7, jloc = p & 127;
            const long gi = ((long)(i0 + il) * NN + jbase + jloc) * 2;
            int4 x0 = A4[gi], x1 = A4[gi + 1];
            unsigned m = (x0.x != 0)
                       | ((x0.y != 0) << 1) | ((x0.z != 0) << 2) | ((x0.w != 0) << 3)
                       | ((x1.x != 0) << 4) | ((x1.y != 0) << 5) | ((x1.z != 0) << 6)
                       | ((x1.w != 0) << 7);
            s_maskb[il * 128 + jloc] = (unsigned char)m;
        }
    }
    __syncthreads();

    // kick chunk-0 copies
    if (t == 0) {
        mbar_expect(u_mbarA, A_TX_BYTES);
        #pragma unroll
        for (int h = 0; h < 8; h++)
            bulk_g2s(u_gl + h * GLSH * 4, Glt + (h * NN + jbase) * 68,
                     GL_SLAB_BYTES, u_mbarA);
        bulk_g2s(u_el, El + jbase * 8, EL_BYTES, u_mbarA);
        mbar_expect(u_mbarB, GR_BYTES);
        bulk_g2s(u_gr, Gr + jbase * 512, GR_BYTES, u_mbarB);
    }

    const float era = s_er[il_a * 8 + h1];
    const float erb = s_er[il_b * 8 + h1];
    const ull ABSM = 0x7FFFFFFF7FFFFFFFULL;
    const float* pA = s_gri + h1 * GIS + il_a * 68;
    const float* pB = pA + 4 * 68;
    const float* pG = s_gl + h1 * GLSH + jl1 * 68;

    ull acc[4][2] = {};

    for (int jc = 0; jc < 8; jc++) {
        const int j0 = jbase + jc * JC;
        const unsigned parity = jc & 1;

        // wait for s_gl + s_el
        mbar_wait(u_mbarA, parity);

        // phase 1: scores for (il_a, il_b) x (j0+jl1) x h1
        {
            ull s0a = 0, s1a = 0, s0b = 0, s1b = 0;
            #pragma unroll
            for (int k = 0; k < 16; k++) {
                ulonglong2 Bv = *(const ulonglong2*)(pG + k * 4);
                ulonglong2 Aa = *(const ulonglong2*)(pA + k * 4);
                ulonglong2 Ab = *(const ulonglong2*)(pB + k * 4);
                ulonglong2 Wv = *(const ulonglong2*)(s_w + k * 4);
                s0a = f2fma(f2add(Aa.x, Bv.x) & ABSM, Wv.x, s0a);
                s1a = f2fma(f2add(Aa.y, Bv.y) & ABSM, Wv.y, s1a);
                s0b = f2fma(f2add(Ab.x, Bv.x) & ABSM, Wv.x, s0b);
                s1b = f2fma(f2add(Ab.y, Bv.y) & ABSM, Wv.y, s1b);
            }
            float2 a0 = upk(s0a), a1 = upk(s1a), b0 = upk(s0b), b1 = upk(s1b);
            const float elv = s_el[jl1 * 8 + h1];
            float ea = era + elv + ((a0.x + a0.y) + (a1.x + a1.y));
            float eb = erb + elv + ((b0.x + b0.y) + (b1.x + b1.y));
            const int jloc = jc * JC + jl1;
            const unsigned ma = s_maskb[il_a * 128 + jloc];
            const unsigned mb = s_maskb[il_b * 128 + jloc];
            ea = ((ma >> h1) & 1) ? ea : -1e30f;
            eb = ((mb >> h1) & 1) ? eb : -1e30f;
            s_e[(il_a * 16 + jl1) * 9 + h1] = ea;
            s_e[(il_b * 16 + jl1) * 9 + h1] = eb;
        }
        __syncthreads();   // s_e ready; s_gl/s_el free

        // kick next chunk's s_gl/s_el copies (overlaps softmax + phase-2)
        if (t == 0 && jc < 7) {
            mbar_expect(u_mbarA, A_TX_BYTES);
            #pragma unroll
            for (int h = 0; h < 8; h++)
                bulk_g2s(u_gl + h * GLSH * 4, Glt + (h * NN + j0 + JC) * 68,
                         GL_SLAB_BYTES, u_mbarA);
            bulk_g2s(u_el, El + (j0 + JC) * 8, EL_BYTES, u_mbarA);
        }

        // softmax over heads: t<128, pair = (il = t>>4, jl = t&15)
        if (t < 128) {
            const int il = t >> 4, jl = t & 15;
            float ev[8];
            #pragma unroll
            for (int h = 0; h < 8; h++) ev[h] = s_e[t * 9 + h];
            float m = ev[0];
            #pragma unroll
            for (int h = 1; h < 8; h++) m = fmaxf(m, ev[h]);
            float ps[8]; float sum = 0.f;
            #pragma unroll
            for (int h = 0; h < 8; h++) { ps[h] = __expf(ev[h] - m); sum += ps[h]; }
            const float rinv = __fdividef(1.0f, sum);
            #pragma unroll
            for (int h = 0; h < 8; h++) s_a[h * SAS + jl * 12 + il] = ps[h] * rinv;
        }

        // wait s_gr completion, then make s_a visible to all
        mbar_wait(u_mbarB, parity);
        __syncthreads();

        // phase 2: thread = (jq j-half, ilh il-quad, c4 cols), 4 il accs
        {
            const int jb = jq * 8;
            #pragma unroll
            for (int jn = 0; jn < 8; jn++) {
                const int jl = jb + jn;
                ulonglong2 g = *(const ulonglong2*)(s_gr + jl * 512 + c4 * 4);
                float4 a4 = *(const float4*)(s_a + h2 * SAS + jl * 12 + ilh * 4);
                ull p0 = pk(a4.x, a4.x), p1 = pk(a4.y, a4.y);
                ull p2 = pk(a4.z, a4.z), p3 = pk(a4.w, a4.w);
                acc[0][0] = f2fma(p0, g.x, acc[0][0]);
                acc[0][1] = f2fma(p0, g.y, acc[0][1]);
                acc[1][0] = f2fma(p1, g.x, acc[1][0]);
                acc[1][1] = f2fma(p1, g.y, acc[1][1]);
                acc[2][0] = f2fma(p2, g.x, acc[2][0]);
                acc[2][1] = f2fma(p2, g.y, acc[2][1]);
                acc[3][0] = f2fma(p3, g.x, acc[3][0]);
                acc[3][1] = f2fma(p3, g.y, acc[3][1]);
            }
        }
        __syncthreads();   // s_gr/s_a free

        if (t == 0 && jc < 7) {
            mbar_expect(u_mbarB, GR_BYTES);
            bulk_g2s(u_gr, Gr + (j0 + JC) * 512, GR_BYTES, u_mbarB);
        }
    }

    // cross-jq reduce, write partial
    if (jq == 1) {
        ull* dst = s_red + (t - 256) * 8;
        #pragma unroll
        for (int il = 0; il < 4; il++) {
            dst[il * 2 + 0] = acc[il][0];
            dst[il * 2 + 1] = acc[il][1];
        }
    }
    __syncthreads();
    if (jq == 0) {
        const ull* src = s_red + t * 8;
        float* P = g_part[jh];
        #pragma unroll
        for (int il = 0; il < 4; il++) {
            float2 lo = upk(f2add(acc[il][0], src[il * 2 + 0]));
            float2 hi = upk(f2add(acc[il][1], src[il * 2 + 1]));
            const int row = b * NN + i0 + ilh * 4 + il;
            *(float4*)(P + row * 512 + c4 * 4) = make_float4(lo.x, lo.y, hi.x, hi.y);
        }
    }

    // ---- tail reduce: second-arriving jh block sums both partials ----
    __threadfence();
    __syncthreads();
    if (t == 0) s_turn = atomicAdd(&g_cnt[b * 32 + it], 1);
    __syncthreads();
    if (s_turn == 1) {
        #pragma unroll
        for (int q = 0; q < 2; q++) {
            const int idx = q * 512 + t;            // 0..1023
            const int rl = idx >> 7, c = idx & 127;
            const int row = b * NN + i0 + rl;
            float4 p0 = __ldcg((const float4*)(g_part[0] + row * 512 + c * 4));
            float4 p1 = __ldcg((const float4*)(g_part[1] + row * 512 + c * 4));
            *(float4*)(out + row * 512 + c * 4) =
                make_float4(p0.x + p1.x, p0.y + p1.y, p0.z + p1.z, p0.w + p1.w);
        }
        if (t == 0) g_cnt[b * 32 + it] = 0;   // reset for next graph replay
    }
}

// ============================================================
extern "C" void kernel_launch(void* const* d_in, const int* in_sizes, int n_in,
                              void* d_out, int out_size) {
    (void)in_sizes; (void)n_in; (void)out_size;
    const float* x   = (const float*)d_in[0];
    const float* Wl  = (const float*)d_in[1];
    const float* Wr  = (const float*)d_in[2];
    const float* aw  = (const float*)d_in[3];
    const int*   adj = (const int*)d_in[4];
    float*       out = (float*)d_out;

    k_gemm<<<dim3(8, 32, 2), 128>>>(x, Wl, Wr, aw);

    const int smem_bytes = SMEM_FLOATS * (int)sizeof(float);
    cudaFuncSetAttribute(k_attn, cudaFuncAttributeMaxDynamicSharedMemorySize, smem_bytes);
    k_attn<<<256, 512, smem_bytes>>>(aw, adj, out);
}

// round 16
// speedup vs baseline: 1.0267x; 1.0267x over previous
#include <cuda_runtime.h>
#include <math.h>

#define BB 4
#define NN 256
#define CC 256
#define HH 8
#define FF 64
#define HF 512

typedef unsigned long long ull;

__device__ float g_glt[BB * HH * NN * 68];  // g_l transposed+padded [b][h][n][68]
__device__ float g_gr[BB * NN * HF];
__device__ float g_el[BB * NN * HH];        // 0.6 * dot(g_l, w), [b][n][h]
__device__ float g_er[BB * NN * HH];        // 0.6 * dot(g_r, w)
__device__ float g_part[2][BB * NN * HF];
__device__ float g_gp[4][BB * NN * HF];     // split-K partials [which*2+kh]
__device__ unsigned g_cnt[BB * 32];         // k_attn tail counters
__device__ unsigned g_gcnt[256];            // gemm split-K counters

// ---- packed f32x2 helpers ----
__device__ __forceinline__ ull f2add(ull a, ull b) {
    ull r; asm("add.rn.f32x2 %0,%1,%2;" : "=l"(r) : "l"(a), "l"(b)); return r;
}
__device__ __forceinline__ ull f2fma(ull a, ull b, ull c) {
    ull r; asm("fma.rn.f32x2 %0,%1,%2,%3;" : "=l"(r) : "l"(a), "l"(b), "l"(c)); return r;
}
__device__ __forceinline__ ull pk(float lo, float hi) {
    ull r; asm("mov.b64 %0,{%1,%2};" : "=l"(r) : "f"(lo), "f"(hi)); return r;
}
__device__ __forceinline__ float2 upk(ull v) {
    float2 r; asm("mov.b64 {%0,%1},%2;" : "=f"(r.x), "=f"(r.y) : "l"(v)); return r;
}
__device__ __forceinline__ unsigned sm_u32(const void* p) {
    unsigned a;
    asm("{ .reg .u64 t; cvta.to.shared.u64 t, %1; cvt.u32.u64 %0, t; }"
        : "=r"(a) : "l"(p));
    return a;
}
__device__ __forceinline__ void mbar_init(unsigned m, unsigned cnt) {
    asm volatile("mbarrier.init.shared.b64 [%0], %1;" :: "r"(m), "r"(cnt) : "memory");
}
__device__ __forceinline__ void mbar_expect(unsigned m, unsigned bytes) {
    asm volatile("mbarrier.arrive.expect_tx.shared.b64 _, [%0], %1;"
                 :: "r"(m), "r"(bytes) : "memory");
}
__device__ __forceinline__ void bulk_g2s(unsigned dst, const void* src,
                                         unsigned bytes, unsigned mbar) {
    asm volatile("cp.async.bulk.shared::cta.global.mbarrier::complete_tx::bytes "
                 "[%0], [%1], %2, [%3];"
                 :: "r"(dst), "l"(src), "r"(bytes), "r"(mbar) : "memory");
}
__device__ __forceinline__ void mbar_wait(unsigned m, unsigned parity) {
    asm volatile(
        "{\n\t"
        ".reg .pred P;\n\t"
        "WL_%=:\n\t"
        "mbarrier.try_wait.parity.acquire.cta.shared::cta.b64 P, [%0], %1, 0x989680;\n\t"
        "@P bra.uni WD_%=;\n\t"
        "bra.uni WL_%=;\n\t"
        "WD_%=:\n\t"
        "}"
        :: "r"(m), "r"(parity) : "memory");
}

// ============================================================
// K1: SGEMM, 64x64 tile, 4x4 packed microtile, BK=32, SPLIT-K=2.
// grid (8,16,4): z = which*2 + kh. Each block does K-half, stores
// partial; second arriver (counter) sums and writes G + epilogue.
// ============================================================
__global__ __launch_bounds__(256) void k_gemm(const float* __restrict__ X,
                                              const float* __restrict__ Wl,
                                              const float* __restrict__ Wr,
                                              const float* __restrict__ attn_w) {
    __shared__ float As[32][68];
    __shared__ float Bs[32][68];
    __shared__ unsigned s_turn;
    const int z = blockIdx.z;
    const int which = z >> 1;
    const int kh = z & 1;
    const float* W = which ? Wr : Wl;
    float* E = which ? g_er : g_el;

    const int t  = threadIdx.x;
    // interleaved map (R10/R14): phase(16 lanes) covers 8 tx x 2 ty
    const int tx = (t >> 1) & 15;
    const int ty = ((t & 1) << 3) | (t >> 5);
    const int m0 = blockIdx.y * 64;
    const int n0 = blockIdx.x * 64;
    const int kbase = kh * 128;

    ull acc[4][2] = {};

    for (int k0 = kbase; k0 < kbase + 128; k0 += 32) {
        {   // stage X tile transposed: 2 float4 per thread
            const int m = t >> 2, kq = (t & 3) * 4;
            #pragma unroll
            for (int half = 0; half < 2; half++) {
                const int kk = kq + half * 16;
                float4 xa = *(const float4*)(X + (m0 + m) * 256 + k0 + kk);
                As[kk + 0][m] = xa.x;
                As[kk + 1][m] = xa.y;
                As[kk + 2][m] = xa.z;
                As[kk + 3][m] = xa.w;
            }
        }
        {   // stage W tile: 2 float4 per thread
            const int k = t >> 4, c = t & 15;
            *(float4*)(&Bs[k][c * 4]) =
                *(const float4*)(W + (k0 + k) * 512 + n0 + c * 4);
            *(float4*)(&Bs[k + 16][c * 4]) =
                *(const float4*)(W + (k0 + k + 16) * 512 + n0 + c * 4);
        }
        __syncthreads();
        #pragma unroll
        for (int k = 0; k < 32; k++) {
            float4 a4 = *(const float4*)(&As[k][ty * 4]);
            ulonglong2 b2 = *(const ulonglong2*)(&Bs[k][tx * 4]);
            ull p0 = pk(a4.x, a4.x), p1 = pk(a4.y, a4.y);
            ull p2 = pk(a4.z, a4.z), p3 = pk(a4.w, a4.w);
            acc[0][0] = f2fma(p0, b2.x, acc[0][0]);
            acc[0][1] = f2fma(p0, b2.y, acc[0][1]);
            acc[1][0] = f2fma(p1, b2.x, acc[1][0]);
            acc[1][1] = f2fma(p1, b2.y, acc[1][1]);
            acc[2][0] = f2fma(p2, b2.x, acc[2][0]);
            acc[2][1] = f2fma(p2, b2.y, acc[2][1]);
            acc[3][0] = f2fma(p3, b2.x, acc[3][0]);
            acc[3][1] = f2fma(p3, b2.y, acc[3][1]);
        }
        __syncthreads();
    }

    // store my partial (bypass L1 so the peer block can read it)
    float* P = g_gp[z];
    #pragma unroll
    for (int i = 0; i < 4; i++) {
        float2 lo = upk(acc[i][0]), hi = upk(acc[i][1]);
        __stcg((float4*)(P + (m0 + ty * 4 + i) * 512 + n0 + tx * 4),
               make_float4(lo.x, lo.y, hi.x, hi.y));
    }
    __threadfence();
    __syncthreads();
    const unsigned cidx = which * 128 + blockIdx.y * 8 + blockIdx.x;
    if (t == 0) s_turn = atomicAdd(&g_gcnt[cidx], 1);
    __syncthreads();
    if (s_turn != 1) return;   // first arriver done

    // second arriver: add peer partial, write final G + epilogue
    const float* Q = g_gp[z ^ 1];
    const int hh = n0 >> 6;
    float af[4][4];
    #pragma unroll
    for (int i = 0; i < 4; i++) {
        const int row = m0 + ty * 4 + i;
        float4 q = __ldcg((const float4*)(Q + row * 512 + n0 + tx * 4));
        float2 lo = upk(acc[i][0]), hi = upk(acc[i][1]);
        af[i][0] = lo.x + q.x; af[i][1] = lo.y + q.y;
        af[i][2] = hi.x + q.z; af[i][3] = hi.y + q.w;
        float4 o = make_float4(af[i][0], af[i][1], af[i][2], af[i][3]);
        if (which) {
            *(float4*)(g_gr + row * 512 + n0 + tx * 4) = o;
        } else {
            const int bb = row >> 8, n = row & 255;
            *(float4*)(g_glt + ((bb * 8 + hh) * 256 + n) * 68 + tx * 4) = o;
        }
    }
    if (t == 0) g_gcnt[cidx] = 0;   // reset for graph replay

    float w0 = attn_w[tx * 4 + 0], w1 = attn_w[tx * 4 + 1];
    float w2 = attn_w[tx * 4 + 2], w3 = attn_w[tx * 4 + 3];
    #pragma unroll
    for (int i = 0; i < 4; i++) {
        float part = af[i][0] * w0;
        part = fmaf(af[i][1], w1, part);
        part = fmaf(af[i][2], w2, part);
        part = fmaf(af[i][3], w3, part);
        part += __shfl_xor_sync(0xffffffff, part, 16);
        part += __shfl_xor_sync(0xffffffff, part, 8);
        part += __shfl_xor_sync(0xffffffff, part, 4);
        part += __shfl_xor_sync(0xffffffff, part, 2);
        if (tx == 0) E[(m0 + ty * 4 + i) * 8 + hh] = 0.6f * part;
    }
}

// ============================================================
// K2: fused attention (exact R10/R14 version). cp.async.bulk
// staging (mbarA: s_gl+s_el, mbarB: s_gr). 512 threads, IT=8,
// j-half per block, JC=16, grid 256.
// ============================================================
#define IT 8
#define JC 16
#define GIS 544      // 8*68  s_gri per-h stride
#define GLSH 1088    // 16*68 s_gl per-h slab (= 4352B, contiguous in g_glt)
#define SAS 200      // s_a per-h stride (jl*12 + il)
#define GL_SLAB_BYTES (JC * 68 * 4)          // 4352
#define EL_BYTES (JC * 8 * 4)                // 512
#define A_TX_BYTES (8 * GL_SLAB_BYTES + EL_BYTES)  // 35328
#define GR_BYTES (JC * 512 * 4)              // 32768

#define SMEM_FLOATS (4352 + 8704 + 8192 + 1152 + 1600 + 64 + 128 + 64 + 256 + 8)

__global__ __launch_bounds__(512, 2) void k_attn(const float* __restrict__ attn_w,
                                                 const int* __restrict__ adj,
                                                 float* __restrict__ out) {
    extern __shared__ float sm[];
    float* s_gri = sm;                   // [h][il*68+f]        4352
    float* s_gl  = s_gri + 4352;         // [h][jl*68+f]        8704
    float* s_gr  = s_gl + 8704;          // [jl][512]           8192
    float* s_e   = s_gr + 8192;          // [(il*16+jl)*9+h]    1152
    float* s_a   = s_e + 1152;           // [h][jl*12+il]       1600
    float* s_w   = s_a + 1600;           // 0.4*w               64
    float* s_el  = s_w + 64;             // [jl][h]             128
    float* s_er  = s_el + 128;           // 64
    float* s_mk  = s_er + 64;            // 256 floats = 1024 mask bytes
    ull*   s_mbars = (ull*)(s_mk + 256); // 2 mbarriers (16B)
    unsigned char* s_maskb = (unsigned char*)s_mk;
    ull*   s_red = (ull*)s_gl;           // aliased reduce buf
    __shared__ unsigned s_turn;

    const int t  = threadIdx.x;
    const int bx = blockIdx.x;
    const int jh = bx & 1;
    const int it = (bx >> 1) & 31;
    const int b  = bx >> 6;
    const int i0 = it * IT;
    const int jbase = jh * 128;

    const float* Gr  = g_gr + b * NN * HF;
    const float* Glt = g_glt + b * HH * NN * 68;
    const float* El  = g_el + b * NN * HH;

    const unsigned u_mbarA = sm_u32(s_mbars);
    const unsigned u_mbarB = sm_u32(s_mbars + 1);
    const unsigned u_gl    = sm_u32(s_gl);
    const unsigned u_gr    = sm_u32(s_gr);
    const unsigned u_el    = sm_u32(s_el);

    // phase-1 ids: warp = (h, ilq); phase holds 8 jl x 2 il
    const int w1 = t >> 5, lane = t & 31;
    const int h1  = w1 >> 1;
    const int ilq = w1 & 1;
    const int il_a = ilq * 2 + (lane & 1);
    const int il_b = il_a + 4;
    const int jl1  = lane >> 1;
    // phase-2 ids
    const int c4  = t & 127;
    const int ilh = (t >> 7) & 1;
    const int jq  = t >> 8;
    const int h2  = c4 >> 4;

    // prologue: mbar init first, then smem staging
    if (t == 0) { mbar_init(u_mbarA, 1); mbar_init(u_mbarB, 1); }
    if (t < 64) s_w[t] = 0.4f * attn_w[t];
    #pragma unroll
    for (int q = 0; q < 2; q++) {
        const int idx = q * 512 + t;
        const int il = idx >> 7, rest = idx & 127, h = rest >> 4, f4 = rest & 15;
        float4 v = *(const float4*)(Gr + (i0 + il) * 512 + rest * 4);
        *(float4*)(s_gri + h * GIS + il * 68 + f4 * 4) = v;
    }
    if (t < 64) s_er[t] = g_er[(b * NN + i0 + (t >> 3)) * 8 + (t & 7)];
    {
        const int4* A4 = (const int4*)adj;
        #pragma unroll
        for (int q = 0; q < 2; q++) {
            const int p = q * 512 + t;           // 0..1023 (il, jloc)
            const int il = p >> 7, jloc = p & 127;
            const long gi = ((long)(i0 + il) * NN + jbase + jloc) * 2;
            int4 x0 = A4[gi], x1 = A4[gi + 1];
            unsigned m = (x0.x != 0)
                       | ((x0.y != 0) << 1) | ((x0.z != 0) << 2) | ((x0.w != 0) << 3)
                       | ((x1.x != 0) << 4) | ((x1.y != 0) << 5) | ((x1.z != 0) << 6)
                       | ((x1.w != 0) << 7);
            s_maskb[il * 128 + jloc] = (unsigned char)m;
        }
    }
    __syncthreads();

    // kick chunk-0 copies
    if (t == 0) {
        mbar_expect(u_mbarA, A_TX_BYTES);
        #pragma unroll
        for (int h = 0; h < 8; h++)
            bulk_g2s(u_gl + h * GLSH * 4, Glt + (h * NN + jbase) * 68,
                     GL_SLAB_BYTES, u_mbarA);
        bulk_g2s(u_el, El + jbase * 8, EL_BYTES, u_mbarA);
        mbar_expect(u_mbarB, GR_BYTES);
        bulk_g2s(u_gr, Gr + jbase * 512, GR_BYTES, u_mbarB);
    }

    const float era = s_er[il_a * 8 + h1];
    const float erb = s_er[il_b * 8 + h1];
    const ull ABSM = 0x7FFFFFFF7FFFFFFFULL;
    const float* pA = s_gri + h1 * GIS + il_a * 68;
    const float* pB = pA + 4 * 68;
    const float* pG = s_gl + h1 * GLSH + jl1 * 68;

    ull acc[4][2] = {};

    for (int jc = 0; jc < 8; jc++) {
        const int j0 = jbase + jc * JC;
        const unsigned parity = jc & 1;

        // wait for s_gl + s_el
        mbar_wait(u_mbarA, parity);

        // phase 1: scores for (il_a, il_b) x (j0+jl1) x h1
        {
            ull s0a = 0, s1a = 0, s0b = 0, s1b = 0;
            #pragma unroll
            for (int k = 0; k < 16; k++) {
                ulonglong2 Bv = *(const ulonglong2*)(pG + k * 4);
                ulonglong2 Aa = *(const ulonglong2*)(pA + k * 4);
                ulonglong2 Ab = *(const ulonglong2*)(pB + k * 4);
                ulonglong2 Wv = *(const ulonglong2*)(s_w + k * 4);
                s0a = f2fma(f2add(Aa.x, Bv.x) & ABSM, Wv.x, s0a);
                s1a = f2fma(f2add(Aa.y, Bv.y) & ABSM, Wv.y, s1a);
                s0b = f2fma(f2add(Ab.x, Bv.x) & ABSM, Wv.x, s0b);
                s1b = f2fma(f2add(Ab.y, Bv.y) & ABSM, Wv.y, s1b);
            }
            float2 a0 = upk(s0a), a1 = upk(s1a), b0 = upk(s0b), b1 = upk(s1b);
            const float elv = s_el[jl1 * 8 + h1];
            float ea = era + elv + ((a0.x + a0.y) + (a1.x + a1.y));
            float eb = erb + elv + ((b0.x + b0.y) + (b1.x + b1.y));
            const int jloc = jc * JC + jl1;
            const unsigned ma = s_maskb[il_a * 128 + jloc];
            const unsigned mb = s_maskb[il_b * 128 + jloc];
            ea = ((ma >> h1) & 1) ? ea : -1e30f;
            eb = ((mb >> h1) & 1) ? eb : -1e30f;
            s_e[(il_a * 16 + jl1) * 9 + h1] = ea;
            s_e[(il_b * 16 + jl1) * 9 + h1] = eb;
        }
        __syncthreads();   // s_e ready; s_gl/s_el free

        // kick next chunk's s_gl/s_el copies (overlaps softmax + phase-2)
        if (t == 0 && jc < 7) {
            mbar_expect(u_mbarA, A_TX_BYTES);
            #pragma unroll
            for (int h = 0; h < 8; h++)
                bulk_g2s(u_gl + h * GLSH * 4, Glt + (h * NN + j0 + JC) * 68,
                         GL_SLAB_BYTES, u_mbarA);
            bulk_g2s(u_el, El + (j0 + JC) * 8, EL_BYTES, u_mbarA);
        }

        // softmax over heads: t<128, pair = (il = t>>4, jl = t&15)
        if (t < 128) {
            const int il = t >> 4, jl = t & 15;
            float ev[8];
            #pragma unroll
            for (int h = 0; h < 8; h++) ev[h] = s_e[t * 9 + h];
            float m = ev[0];
            #pragma unroll
            for (int h = 1; h < 8; h++) m = fmaxf(m, ev[h]);
            float ps[8]; float sum = 0.f;
            #pragma unroll
            for (int h = 0; h < 8; h++) { ps[h] = __expf(ev[h] - m); sum += ps[h]; }
            const float rinv = __fdividef(1.0f, sum);
            #pragma unroll
            for (int h = 0; h < 8; h++) s_a[h * SAS + jl * 12 + il] = ps[h] * rinv;
        }

        // wait s_gr completion, then make s_a visible to all
        mbar_wait(u_mbarB, parity);
        __syncthreads();

        // phase 2: thread = (jq j-half, ilh il-quad, c4 cols), 4 il accs
        {
            const int jb = jq * 8;
            #pragma unroll
            for (int jn = 0; jn < 8; jn++) {
                const int jl = jb + jn;
                ulonglong2 g = *(const ulonglong2*)(s_gr + jl * 512 + c4 * 4);
                float4 a4 = *(const float4*)(s_a + h2 * SAS + jl * 12 + ilh * 4);
                ull p0 = pk(a4.x, a4.x), p1 = pk(a4.y, a4.y);
                ull p2 = pk(a4.z, a4.z), p3 = pk(a4.w, a4.w);
                acc[0][0] = f2fma(p0, g.x, acc[0][0]);
                acc[0][1] = f2fma(p0, g.y, acc[0][1]);
                acc[1][0] = f2fma(p1, g.x, acc[1][0]);
                acc[1][1] = f2fma(p1, g.y, acc[1][1]);
                acc[2][0] = f2fma(p2, g.x, acc[2][0]);
                acc[2][1] = f2fma(p2, g.y, acc[2][1]);
                acc[3][0] = f2fma(p3, g.x, acc[3][0]);
                acc[3][1] = f2fma(p3, g.y, acc[3][1]);
            }
        }
        __syncthreads();   // s_gr/s_a free

        if (t == 0 && jc < 7) {
            mbar_expect(u_mbarB, GR_BYTES);
            bulk_g2s(u_gr, Gr + (j0 + JC) * 512, GR_BYTES, u_mbarB);
        }
    }

    // cross-jq reduce, write partial
    if (jq == 1) {
        ull* dst = s_red + (t - 256) * 8;
        #pragma unroll
        for (int il = 0; il < 4; il++) {
            dst[il * 2 + 0] = acc[il][0];
            dst[il * 2 + 1] = acc[il][1];
        }
    }
    __syncthreads();
    if (jq == 0) {
        const ull* src = s_red + t * 8;
        float* P = g_part[jh];
        #pragma unroll
        for (int il = 0; il < 4; il++) {
            float2 lo = upk(f2add(acc[il][0], src[il * 2 + 0]));
            float2 hi = upk(f2add(acc[il][1], src[il * 2 + 1]));
            const int row = b * NN + i0 + ilh * 4 + il;
            *(float4*)(P + row * 512 + c4 * 4) = make_float4(lo.x, lo.y, hi.x, hi.y);
        }
    }

    // ---- tail reduce: second-arriving jh block sums both partials ----
    __threadfence();
    __syncthreads();
    if (t == 0) s_turn = atomicAdd(&g_cnt[b * 32 + it], 1);
    __syncthreads();
    if (s_turn == 1) {
        #pragma unroll
        for (int q = 0; q < 2; q++) {
            const int idx = q * 512 + t;            // 0..1023
            const int rl = idx >> 7, c = idx & 127;
            const int row = b * NN + i0 + rl;
            float4 p0 = __ldcg((const float4*)(g_part[0] + row * 512 + c * 4));
            float4 p1 = __ldcg((const float4*)(g_part[1] + row * 512 + c * 4));
            *(float4*)(out + row * 512 + c * 4) =
                make_float4(p0.x + p1.x, p0.y + p1.y, p0.z + p1.z, p0.w + p1.w);
        }
        if (t == 0) g_cnt[b * 32 + it] = 0;   // reset for next graph replay
    }
}

// ============================================================
extern "C" void kernel_launch(void* const* d_in, const int* in_sizes, int n_in,
                              void* d_out, int out_size) {
    (void)in_sizes; (void)n_in; (void)out_size;
    const float* x   = (const float*)d_in[0];
    const float* Wl  = (const float*)d_in[1];
    const float* Wr  = (const float*)d_in[2];
    const float* aw  = (const float*)d_in[3];
    const int*   adj = (const int*)d_in[4];
    float*       out = (float*)d_out;

    k_gemm<<<dim3(8, 16, 4), 256>>>(x, Wl, Wr, aw);

    const int smem_bytes = SMEM_FLOATS * (int)sizeof(float);
    cudaFuncSetAttribute(k_attn, cudaFuncAttributeMaxDynamicSharedMemorySize, smem_bytes);
    k_attn<<<256, 512, smem_bytes>>>(aw, adj, out);
}

// round 17
// speedup vs baseline: 1.0590x; 1.0314x over previous
#include <cuda_runtime.h>
#include <math.h>

#define BB 4
#define NN 256
#define CC 256
#define HH 8
#define FF 64
#define HF 512

typedef unsigned long long ull;

__device__ float g_glt[BB * HH * NN * 68];  // g_l transposed+padded [b][h][n][68]
__device__ float g_gr[BB * NN * HF];
__device__ float g_el[BB * NN * HH];        // 0.6 * dot(g_l, w), [b][n][h]
__device__ float g_er[BB * NN * HH];        // 0.6 * dot(g_r, w)
__device__ float g_part[2][BB * NN * HF];
__device__ unsigned g_cnt[BB * 32];         // zero-init; reset after use

// ---- packed f32x2 helpers ----
__device__ __forceinline__ ull f2add(ull a, ull b) {
    ull r; asm("add.rn.f32x2 %0,%1,%2;" : "=l"(r) : "l"(a), "l"(b)); return r;
}
__device__ __forceinline__ ull f2fma(ull a, ull b, ull c) {
    ull r; asm("fma.rn.f32x2 %0,%1,%2,%3;" : "=l"(r) : "l"(a), "l"(b), "l"(c)); return r;
}
__device__ __forceinline__ ull pk(float lo, float hi) {
    ull r; asm("mov.b64 %0,{%1,%2};" : "=l"(r) : "f"(lo), "f"(hi)); return r;
}
__device__ __forceinline__ float2 upk(ull v) {
    float2 r; asm("mov.b64 {%0,%1},%2;" : "=f"(r.x), "=f"(r.y) : "l"(v)); return r;
}
__device__ __forceinline__ unsigned sm_u32(const void* p) {
    unsigned a;
    asm("{ .reg .u64 t; cvta.to.shared.u64 t, %1; cvt.u32.u64 %0, t; }"
        : "=r"(a) : "l"(p));
    return a;
}
__device__ __forceinline__ void mbar_init(unsigned m, unsigned cnt) {
    asm volatile("mbarrier.init.shared.b64 [%0], %1;" :: "r"(m), "r"(cnt) : "memory");
}
__device__ __forceinline__ void mbar_expect(unsigned m, unsigned bytes) {
    asm volatile("mbarrier.arrive.expect_tx.shared.b64 _, [%0], %1;"
                 :: "r"(m), "r"(bytes) : "memory");
}
__device__ __forceinline__ void bulk_g2s(unsigned dst, const void* src,
                                         unsigned bytes, unsigned mbar) {
    asm volatile("cp.async.bulk.shared::cta.global.mbarrier::complete_tx::bytes "
                 "[%0], [%1], %2, [%3];"
                 :: "r"(dst), "l"(src), "r"(bytes), "r"(mbar) : "memory");
}
__device__ __forceinline__ void mbar_wait(unsigned m, unsigned parity) {
    asm volatile(
        "{\n\t"
        ".reg .pred P;\n\t"
        "WL_%=:\n\t"
        "mbarrier.try_wait.parity.acquire.cta.shared::cta.b64 P, [%0], %1, 0x989680;\n\t"
        "@P bra.uni WD_%=;\n\t"
        "bra.uni WL_%=;\n\t"
        "WD_%=:\n\t"
        "}"
        :: "r"(m), "r"(parity) : "memory");
}

// ============================================================
// K1: SGEMM, 64x64 tile, 4x4 packed microtile, BK=64 (8 barriers
// per block; 8 outstanding LDGs per staging step).
// which=0 -> g_glt (transposed/padded); which=1 -> g_gr.
// Fused 0.6*dot(g,w) epilogue.
// ============================================================
__global__ __launch_bounds__(256) void k_gemm(const float* __restrict__ X,
                                              const float* __restrict__ Wl,
                                              const float* __restrict__ Wr,
                                              const float* __restrict__ attn_w) {
    __shared__ float As[64][68];
    __shared__ float Bs[64][68];
    const int which = blockIdx.z;
    const float* W = which ? Wr : Wl;
    float* E = which ? g_er : g_el;

    const int t  = threadIdx.x;
    // interleaved map (R10/R14): phase(16 lanes) covers 8 tx x 2 ty
    const int tx = (t >> 1) & 15;
    const int ty = ((t & 1) << 3) | (t >> 5);
    const int m0 = blockIdx.y * 64;
    const int n0 = blockIdx.x * 64;

    ull acc[4][2] = {};

    for (int k0 = 0; k0 < 256; k0 += 64) {
        {   // stage X tile transposed: 4 float4 per thread
            const int m = t >> 2, kq = (t & 3) * 4;
            #pragma unroll
            for (int half = 0; half < 4; half++) {
                const int kk = kq + half * 16;
                float4 xa = *(const float4*)(X + (m0 + m) * 256 + k0 + kk);
                As[kk + 0][m] = xa.x;
                As[kk + 1][m] = xa.y;
                As[kk + 2][m] = xa.z;
                As[kk + 3][m] = xa.w;
            }
        }
        {   // stage W tile: 4 float4 per thread
            const int k = t >> 4, c = t & 15;
            #pragma unroll
            for (int half = 0; half < 4; half++) {
                *(float4*)(&Bs[k + half * 16][c * 4]) =
                    *(const float4*)(W + (k0 + k + half * 16) * 512 + n0 + c * 4);
            }
        }
        __syncthreads();
        #pragma unroll
        for (int k = 0; k < 64; k++) {
            float4 a4 = *(const float4*)(&As[k][ty * 4]);
            ulonglong2 b2 = *(const ulonglong2*)(&Bs[k][tx * 4]);
            ull p0 = pk(a4.x, a4.x), p1 = pk(a4.y, a4.y);
            ull p2 = pk(a4.z, a4.z), p3 = pk(a4.w, a4.w);
            acc[0][0] = f2fma(p0, b2.x, acc[0][0]);
            acc[0][1] = f2fma(p0, b2.y, acc[0][1]);
            acc[1][0] = f2fma(p1, b2.x, acc[1][0]);
            acc[1][1] = f2fma(p1, b2.y, acc[1][1]);
            acc[2][0] = f2fma(p2, b2.x, acc[2][0]);
            acc[2][1] = f2fma(p2, b2.y, acc[2][1]);
            acc[3][0] = f2fma(p3, b2.x, acc[3][0]);
            acc[3][1] = f2fma(p3, b2.y, acc[3][1]);
        }
        __syncthreads();
    }

    const int hh = n0 >> 6;
    float af[4][4];
    #pragma unroll
    for (int i = 0; i < 4; i++) {
        float2 lo = upk(acc[i][0]), hi = upk(acc[i][1]);
        af[i][0] = lo.x; af[i][1] = lo.y; af[i][2] = hi.x; af[i][3] = hi.y;
        const int row = m0 + ty * 4 + i;
        float4 o = make_float4(lo.x, lo.y, hi.x, hi.y);
        if (which) {
            *(float4*)(g_gr + row * 512 + n0 + tx * 4) = o;
        } else {
            const int bb = row >> 8, n = row & 255;
            *(float4*)(g_glt + ((bb * 8 + hh) * 256 + n) * 68 + tx * 4) = o;
        }
    }

    float w0 = attn_w[tx * 4 + 0], w1 = attn_w[tx * 4 + 1];
    float w2 = attn_w[tx * 4 + 2], w3 = attn_w[tx * 4 + 3];
    #pragma unroll
    for (int i = 0; i < 4; i++) {
        float part = af[i][0] * w0;
        part = fmaf(af[i][1], w1, part);
        part = fmaf(af[i][2], w2, part);
        part = fmaf(af[i][3], w3, part);
        part += __shfl_xor_sync(0xffffffff, part, 16);
        part += __shfl_xor_sync(0xffffffff, part, 8);
        part += __shfl_xor_sync(0xffffffff, part, 4);
        part += __shfl_xor_sync(0xffffffff, part, 2);
        if (tx == 0) E[(m0 + ty * 4 + i) * 8 + hh] = 0.6f * part;
    }
}

// ============================================================
// K2: fused attention (exact R10/R14 version). cp.async.bulk
// staging (mbarA: s_gl+s_el, mbarB: s_gr). 512 threads, IT=8,
// j-half per block, JC=16, grid 256.
// ============================================================
#define IT 8
#define JC 16
#define GIS 544      // 8*68  s_gri per-h stride
#define GLSH 1088    // 16*68 s_gl per-h slab (= 4352B, contiguous in g_glt)
#define SAS 200      // s_a per-h stride (jl*12 + il)
#define GL_SLAB_BYTES (JC * 68 * 4)          // 4352
#define EL_BYTES (JC * 8 * 4)                // 512
#define A_TX_BYTES (8 * GL_SLAB_BYTES + EL_BYTES)  // 35328
#define GR_BYTES (JC * 512 * 4)              // 32768

#define SMEM_FLOATS (4352 + 8704 + 8192 + 1152 + 1600 + 64 + 128 + 64 + 256 + 8)

__global__ __launch_bounds__(512, 2) void k_attn(const float* __restrict__ attn_w,
                                                 const int* __restrict__ adj,
                                                 float* __restrict__ out) {
    extern __shared__ float sm[];
    float* s_gri = sm;                   // [h][il*68+f]        4352
    float* s_gl  = s_gri + 4352;         // [h][jl*68+f]        8704
    float* s_gr  = s_gl + 8704;          // [jl][512]           8192
    float* s_e   = s_gr + 8192;          // [(il*16+jl)*9+h]    1152
    float* s_a   = s_e + 1152;           // [h][jl*12+il]       1600
    float* s_w   = s_a + 1600;           // 0.4*w               64
    float* s_el  = s_w + 64;             // [jl][h]             128
    float* s_er  = s_el + 128;           // 64
    float* s_mk  = s_er + 64;            // 256 floats = 1024 mask bytes
    ull*   s_mbars = (ull*)(s_mk + 256); // 2 mbarriers (16B)
    unsigned char* s_maskb = (unsigned char*)s_mk;
    ull*   s_red = (ull*)s_gl;           // aliased reduce buf
    __shared__ unsigned s_turn;

    const int t  = threadIdx.x;
    const int bx = blockIdx.x;
    const int jh = bx & 1;
    const int it = (bx >> 1) & 31;
    const int b  = bx >> 6;
    const int i0 = it * IT;
    const int jbase = jh * 128;

    const float* Gr  = g_gr + b * NN * HF;
    const float* Glt = g_glt + b * HH * NN * 68;
    const float* El  = g_el + b * NN * HH;

    const unsigned u_mbarA = sm_u32(s_mbars);
    const unsigned u_mbarB = sm_u32(s_mbars + 1);
    const unsigned u_gl    = sm_u32(s_gl);
    const unsigned u_gr    = sm_u32(s_gr);
    const unsigned u_el    = sm_u32(s_el);

    // phase-1 ids: warp = (h, ilq); phase holds 8 jl x 2 il
    const int w1 = t >> 5, lane = t & 31;
    const int h1  = w1 >> 1;
    const int ilq = w1 & 1;
    const int il_a = ilq * 2 + (lane & 1);
    const int il_b = il_a + 4;
    const int jl1  = lane >> 1;
    // phase-2 ids
    const int c4  = t & 127;
    const int ilh = (t >> 7) & 1;
    const int jq  = t >> 8;
    const int h2  = c4 >> 4;

    // prologue: mbar init first, then smem staging
    if (t == 0) { mbar_init(u_mbarA, 1); mbar_init(u_mbarB, 1); }
    if (t < 64) s_w[t] = 0.4f * attn_w[t];
    #pragma unroll
    for (int q = 0; q < 2; q++) {
        const int idx = q * 512 + t;
        const int il = idx >> 7, rest = idx & 127, h = rest >> 4, f4 = rest & 15;
        float4 v = *(const float4*)(Gr + (i0 + il) * 512 + rest * 4);
        *(float4*)(s_gri + h * GIS + il * 68 + f4 * 4) = v;
    }
    if (t < 64) s_er[t] = g_er[(b * NN + i0 + (t >> 3)) * 8 + (t & 7)];
    {
        const int4* A4 = (const int4*)adj;
        #pragma unroll
        for (int q = 0; q < 2; q++) {
            const int p = q * 512 + t;           // 0..1023 (il, jloc)
            const int il = p >> 7, jloc = p & 127;
            const long gi = ((long)(i0 + il) * NN + jbase + jloc) * 2;
            int4 x0 = A4[gi], x1 = A4[gi + 1];
            unsigned m = (x0.x != 0)
                       | ((x0.y != 0) << 1) | ((x0.z != 0) << 2) | ((x0.w != 0) << 3)
                       | ((x1.x != 0) << 4) | ((x1.y != 0) << 5) | ((x1.z != 0) << 6)
                       | ((x1.w != 0) << 7);
            s_maskb[il * 128 + jloc] = (unsigned char)m;
        }
    }
    __syncthreads();

    // kick chunk-0 copies
    if (t == 0) {
        mbar_expect(u_mbarA, A_TX_BYTES);
        #pragma unroll
        for (int h = 0; h < 8; h++)
            bulk_g2s(u_gl + h * GLSH * 4, Glt + (h * NN + jbase) * 68,
                     GL_SLAB_BYTES, u_mbarA);
        bulk_g2s(u_el, El + jbase * 8, EL_BYTES, u_mbarA);
        mbar_expect(u_mbarB, GR_BYTES);
        bulk_g2s(u_gr, Gr + jbase * 512, GR_BYTES, u_mbarB);
    }

    const float era = s_er[il_a * 8 + h1];
    const float erb = s_er[il_b * 8 + h1];
    const ull ABSM = 0x7FFFFFFF7FFFFFFFULL;
    const float* pA = s_gri + h1 * GIS + il_a * 68;
    const float* pB = pA + 4 * 68;
    const float* pG = s_gl + h1 * GLSH + jl1 * 68;

    ull acc[4][2] = {};

    for (int jc = 0; jc < 8; jc++) {
        const int j0 = jbase + jc * JC;
        const unsigned parity = jc & 1;

        // wait for s_gl + s_el
        mbar_wait(u_mbarA, parity);

        // phase 1: scores for (il_a, il_b) x (j0+jl1) x h1
        {
            ull s0a = 0, s1a = 0, s0b = 0, s1b = 0;
            #pragma unroll
            for (int k = 0; k < 16; k++) {
                ulonglong2 Bv = *(const ulonglong2*)(pG + k * 4);
                ulonglong2 Aa = *(const ulonglong2*)(pA + k * 4);
                ulonglong2 Ab = *(const ulonglong2*)(pB + k * 4);
                ulonglong2 Wv = *(const ulonglong2*)(s_w + k * 4);
                s0a = f2fma(f2add(Aa.x, Bv.x) & ABSM, Wv.x, s0a);
                s1a = f2fma(f2add(Aa.y, Bv.y) & ABSM, Wv.y, s1a);
                s0b = f2fma(f2add(Ab.x, Bv.x) & ABSM, Wv.x, s0b);
                s1b = f2fma(f2add(Ab.y, Bv.y) & ABSM, Wv.y, s1b);
            }
            float2 a0 = upk(s0a), a1 = upk(s1a), b0 = upk(s0b), b1 = upk(s1b);
            const float elv = s_el[jl1 * 8 + h1];
            float ea = era + elv + ((a0.x + a0.y) + (a1.x + a1.y));
            float eb = erb + elv + ((b0.x + b0.y) + (b1.x + b1.y));
            const int jloc = jc * JC + jl1;
            const unsigned ma = s_maskb[il_a * 128 + jloc];
            const unsigned mb = s_maskb[il_b * 128 + jloc];
            ea = ((ma >> h1) & 1) ? ea : -1e30f;
            eb = ((mb >> h1) & 1) ? eb : -1e30f;
            s_e[(il_a * 16 + jl1) * 9 + h1] = ea;
            s_e[(il_b * 16 + jl1) * 9 + h1] = eb;
        }
        __syncthreads();   // s_e ready; s_gl/s_el free

        // kick next chunk's s_gl/s_el copies (overlaps softmax + phase-2)
        if (t == 0 && jc < 7) {
            mbar_expect(u_mbarA, A_TX_BYTES);
            #pragma unroll
            for (int h = 0; h < 8; h++)
                bulk_g2s(u_gl + h * GLSH * 4, Glt + (h * NN + j0 + JC) * 68,
                         GL_SLAB_BYTES, u_mbarA);
            bulk_g2s(u_el, El + (j0 + JC) * 8, EL_BYTES, u_mbarA);
        }

        // softmax over heads: t<128, pair = (il = t>>4, jl = t&15)
        if (t < 128) {
            const int il = t >> 4, jl = t & 15;
            float ev[8];
            #pragma unroll
            for (int h = 0; h < 8; h++) ev[h] = s_e[t * 9 + h];
            float m = ev[0];
            #pragma unroll
            for (int h = 1; h < 8; h++) m = fmaxf(m, ev[h]);
            float ps[8]; float sum = 0.f;
            #pragma unroll
            for (int h = 0; h < 8; h++) { ps[h] = __expf(ev[h] - m); sum += ps[h]; }
            const float rinv = __fdividef(1.0f, sum);
            #pragma unroll
            for (int h = 0; h < 8; h++) s_a[h * SAS + jl * 12 + il] = ps[h] * rinv;
        }

        // wait s_gr completion, then make s_a visible to all
        mbar_wait(u_mbarB, parity);
        __syncthreads();

        // phase 2: thread = (jq j-half, ilh il-quad, c4 cols), 4 il accs
        {
            const int jb = jq * 8;
            #pragma unroll
            for (int jn = 0; jn < 8; jn++) {
                const int jl = jb + jn;
                ulonglong2 g = *(const ulonglong2*)(s_gr + jl * 512 + c4 * 4);
                float4 a4 = *(const float4*)(s_a + h2 * SAS + jl * 12 + ilh * 4);
                ull p0 = pk(a4.x, a4.x), p1 = pk(a4.y, a4.y);
                ull p2 = pk(a4.z, a4.z), p3 = pk(a4.w, a4.w);
                acc[0][0] = f2fma(p0, g.x, acc[0][0]);
                acc[0][1] = f2fma(p0, g.y, acc[0][1]);
                acc[1][0] = f2fma(p1, g.x, acc[1][0]);
                acc[1][1] = f2fma(p1, g.y, acc[1][1]);
                acc[2][0] = f2fma(p2, g.x, acc[2][0]);
                acc[2][1] = f2fma(p2, g.y, acc[2][1]);
                acc[3][0] = f2fma(p3, g.x, acc[3][0]);
                acc[3][1] = f2fma(p3, g.y, acc[3][1]);
            }
        }
        __syncthreads();   // s_gr/s_a free

        if (t == 0 && jc < 7) {
            mbar_expect(u_mbarB, GR_BYTES);
            bulk_g2s(u_gr, Gr + (j0 + JC) * 512, GR_BYTES, u_mbarB);
        }
    }

    // cross-jq reduce, write partial
    if (jq == 1) {
        ull* dst = s_red + (t - 256) * 8;
        #pragma unroll
        for (int il = 0; il < 4; il++) {
            dst[il * 2 + 0] = acc[il][0];
            dst[il * 2 + 1] = acc[il][1];
        }
    }
    __syncthreads();
    if (jq == 0) {
        const ull* src = s_red + t * 8;
        float* P = g_part[jh];
        #pragma unroll
        for (int il = 0; il < 4; il++) {
            float2 lo = upk(f2add(acc[il][0], src[il * 2 + 0]));
            float2 hi = upk(f2add(acc[il][1], src[il * 2 + 1]));
            const int row = b * NN + i0 + ilh * 4 + il;
            *(float4*)(P + row * 512 + c4 * 4) = make_float4(lo.x, lo.y, hi.x, hi.y);
        }
    }

    // ---- tail reduce: second-arriving jh block sums both partials ----
    __threadfence();
    __syncthreads();
    if (t == 0) s_turn = atomicAdd(&g_cnt[b * 32 + it], 1);
    __syncthreads();
    if (s_turn == 1) {
        #pragma unroll
        for (int q = 0; q < 2; q++) {
            const int idx = q * 512 + t;            // 0..1023
            const int rl = idx >> 7, c = idx & 127;
            const int row = b * NN + i0 + rl;
            float4 p0 = __ldcg((const float4*)(g_part[0] + row * 512 + c * 4));
            float4 p1 = __ldcg((const float4*)(g_part[1] + row * 512 + c * 4));
            *(float4*)(out + row * 512 + c * 4) =
                make_float4(p0.x + p1.x, p0.y + p1.y, p0.z + p1.z, p0.w + p1.w);
        }
        if (t == 0) g_cnt[b * 32 + it] = 0;   // reset for next graph replay
    }
}

// ============================================================
extern "C" void kernel_launch(void* const* d_in, const int* in_sizes, int n_in,
                              void* d_out, int out_size) {
    (void)in_sizes; (void)n_in; (void)out_size;
    const float* x   = (const float*)d_in[0];
    const float* Wl  = (const float*)d_in[1];
    const float* Wr  = (const float*)d_in[2];
    const float* aw  = (const float*)d_in[3];
    const int*   adj = (const int*)d_in[4];
    float*       out = (float*)d_out;

    k_gemm<<<dim3(8, 16, 2), 256>>>(x, Wl, Wr, aw);

    const int smem_bytes = SMEM_FLOATS * (int)sizeof(float);
    cudaFuncSetAttribute(k_attn, cudaFuncAttributeMaxDynamicSharedMemorySize, smem_bytes);
    k_attn<<<256, 512, smem_bytes>>>(aw, adj, out);
}